// round 3
// baseline (speedup 1.0000x reference)
#include <cuda_runtime.h>
#include <cuda_bf16.h>

// LocalitySensitiveHashing_29111288333011
//
// Mathematical collapse of the reference (holds for ALL inputs):
//   qh, kh = sign(...)  ->  {-1, 0, +1}
//   einsum('bqhk,bkhk->bhqk') has no contracted index (repeated k = diagonal),
//   so sim is an elementwise product in {-1,0,+1}, then /HB (2048) and
//   mean over H=8 heads  ->  |sim| <= 1/2048 = 4.88e-4 < SIM_THRESHOLD=0.3.
//   (sim > 0.3) is identically False  ->  output == zeros([2,2048,2048]).
//
// R1/R2 evidence: a pure STG.128 zero-fill is pinned at exactly 7.808 us
// (4.3 TB/s) regardless of launch shape -> byte-stream wall on the SM store
// path. This round: route the fill through a CUDA-graph MEMSET node
// (cudaMemsetAsync under stream capture) so the driver's tuned fill path /
// L2 write aggregation services it instead of 2M discrete STG.128s.
//
// Graph-legality: memset nodes are first-class graph nodes; no allocation,
// no sync, deterministic. Fallback kernel retained (unused) in case a future
// round needs to revert.

__global__ void lsh_zero_fallback_kernel(float4* __restrict__ out, long long n4) {
    long long i = (long long)blockIdx.x * blockDim.x + threadIdx.x;
    if (i < n4) out[i] = make_float4(0.0f, 0.0f, 0.0f, 0.0f);
}

extern "C" void kernel_launch(void* const* d_in, const int* in_sizes, int n_in,
                              void* d_out, int out_size) {
    (void)d_in; (void)in_sizes; (void)n_in;

    // Output dtype is float32; zero bit-pattern is 0x00000000, so a byte-wise
    // memset of 0 produces exactly zeros([2,2048,2048], f32).
    size_t bytes = (size_t)out_size * sizeof(float);
    cudaMemsetAsync(d_out, 0, bytes, 0);
}